// round 9
// baseline (speedup 1.0000x reference)
#include <cuda_runtime.h>
#include <cuda_fp16.h>
#include <cstdint>

// Fused int4 group-dequant + GEMM via fp16 mma.sync with fp16 ACCUMULATORS.
// Round 9: round-7 shell (128x128 tile, 8 warps, 3-stage cp.async, 2 CTA/SM);
// accumulate each BK=64 k-tile in fp16 regs (hypothesis: f16-acc HMMA is
// 2x rate of f32-acc on the sm_103 legacy tensor path), promote to fp32
// accumulators once per tile. Error model: +~4.4e-4 accum noise -> ~6e-4 total.

namespace {

constexpr int MMAX = 8192, NMAX = 4096, KMAX = 4096;

__device__ __half g_X[(size_t)MMAX * KMAX];
__device__ __half g_W[(size_t)NMAX * KMAX];

constexpr int BM = 128, BN = 128, BK = 64;
constexpr int THREADS = 256;
constexpr int ROWB = 144;                 // 64 fp16 = 128B + 16B pad
constexpr int A_OFF = 0;
constexpr int B_OFF = BM * ROWB;          // 18432
constexpr int STAGE = B_OFF + BN * ROWB;  // 36864
constexpr int NSTAGES = 3;
constexpr int SMEM_TOTAL = NSTAGES * STAGE;  // 110592 -> 2 CTAs/SM

__device__ __forceinline__ uint32_t smem_u32(const void* p) {
    uint32_t a;
    asm("{ .reg .u64 t; cvta.to.shared.u64 t, %1; cvt.u32.u64 %0, t; }"
        : "=r"(a) : "l"(p));
    return a;
}
__device__ __forceinline__ void cp16(uint32_t dst, const void* src) {
    asm volatile("cp.async.cg.shared.global [%0], [%1], 16;"
                 :: "r"(dst), "l"(src) : "memory");
}
#define CP_COMMIT() asm volatile("cp.async.commit_group;" ::: "memory")
#define CP_WAIT(n)  asm volatile("cp.async.wait_group %0;" :: "n"(n) : "memory")

__device__ __forceinline__ void ldsm_x4(uint32_t* r, uint32_t addr) {
    asm volatile("ldmatrix.sync.aligned.m8n8.x4.shared.b16 {%0,%1,%2,%3}, [%4];"
                 : "=r"(r[0]), "=r"(r[1]), "=r"(r[2]), "=r"(r[3]) : "r"(addr));
}
// fp16-accumulator HMMA
__device__ __forceinline__ void mma_fp16_hacc(uint32_t* c, const uint32_t* a,
                                              const uint32_t* b) {
    asm volatile(
        "mma.sync.aligned.m16n8k16.row.col.f16.f16.f16.f16 "
        "{%0,%1}, {%2,%3,%4,%5}, {%6,%7}, {%0,%1};"
        : "+r"(c[0]), "+r"(c[1])
        : "r"(a[0]), "r"(a[1]), "r"(a[2]), "r"(a[3]), "r"(b[0]), "r"(b[1]));
}

// ---- pre-pass: x -> fp16 ----
__global__ __launch_bounds__(256)
void convert_x_kernel(const float* __restrict__ X, long total4) {
    long i = (long)blockIdx.x * blockDim.x + threadIdx.x;
    if (i >= total4) return;
    float4 v = reinterpret_cast<const float4*>(X)[i];
    __half2* H = reinterpret_cast<__half2*>(g_X);
    H[2 * i]     = __floats2half2_rn(v.x, v.y);
    H[2 * i + 1] = __floats2half2_rn(v.z, v.w);
}

// ---- pre-pass: dequant W (int4, group scale/zp) -> fp16 ----
__global__ __launch_bounds__(256)
void convert_w_kernel(const int* __restrict__ QW, const float* __restrict__ SC,
                      const float* __restrict__ ZP, int wordsPerRow, int nGroups,
                      long totalWords) {
    long i = (long)blockIdx.x * blockDim.x + threadIdx.x;
    if (i >= totalWords) return;
    int n = (int)(i / wordsPerRow);
    int w = (int)(i % wordsPerRow);
    int g = (w * 8) >> 7;  // group_size 128 = 16 int32 words
    float s = SC[(size_t)n * nGroups + g];
    float z = ZP[(size_t)n * nGroups + g];
    float szn = -s * z;
    unsigned q = (unsigned)QW[i];
    __half2 h[4];
#pragma unroll
    for (int j = 0; j < 4; j++) {
        float f0 = fmaf(s, (float)((q >> (8 * j)) & 0xFu), szn);
        float f1 = fmaf(s, (float)((q >> (8 * j + 4)) & 0xFu), szn);
        h[j] = __floats2half2_rn(f0, f1);
    }
    reinterpret_cast<uint2*>(g_W)[2 * i]     = *reinterpret_cast<uint2*>(&h[0]);
    reinterpret_cast<uint2*>(g_W)[2 * i + 1] = *reinterpret_cast<uint2*>(&h[2]);
}

// ---- main GEMM: 128x128 CTA, BK=64, 8 warps (2x4), warp tile 64x32 ----
__global__ __launch_bounds__(THREADS, 2)
void gemm_kernel(const float* __restrict__ BIAS, float* __restrict__ Y,
                 int M, int N, int K) {
    extern __shared__ char smem[];
    const uint32_t su = smem_u32(smem);
    const int tid  = threadIdx.x;
    const int lane = tid & 31;
    const int wid  = tid >> 5;
    const int bm = blockIdx.y * BM;
    const int bn = blockIdx.x * BN;
    const int mw = (wid >> 2) * 64;   // 2 warps along m
    const int nw = (wid & 3) * 32;    // 4 warps along n

    auto load_stage = [&](int s, int t) {
        const uint32_t sb = su + s * STAGE;
        const size_t k0 = (size_t)t * BK;
#pragma unroll
        for (int j = 0; j < 4; j++) {  // A: 128 rows x 8 x 16B
            int idx = tid + j * THREADS;
            int r = idx >> 3, c = idx & 7;
            cp16(sb + A_OFF + (uint32_t)(r * ROWB + c * 16),
                 (const char*)(g_X + (size_t)(bm + r) * K + k0) + c * 16);
        }
#pragma unroll
        for (int j = 0; j < 4; j++) {  // B: 128 rows x 8 x 16B
            int idx = tid + j * THREADS;
            int r = idx >> 3, c = idx & 7;
            cp16(sb + B_OFF + (uint32_t)(r * ROWB + c * 16),
                 (const char*)(g_W + (size_t)(bn + r) * K + k0) + c * 16);
        }
        CP_COMMIT();
    };

    float acc[4][4][4];
#pragma unroll
    for (int i = 0; i < 4; i++)
#pragma unroll
        for (int j = 0; j < 4; j++)
#pragma unroll
            for (int c = 0; c < 4; c++) acc[i][j][c] = 0.f;

    const int T = K / BK;  // 64
    load_stage(0, 0);
    load_stage(1, 1);

    // ldmatrix lane addressing
    const uint32_t a_r  = (uint32_t)((lane & 7) + ((lane >> 3) & 1) * 8);
    const uint32_t a_cb = (uint32_t)(((lane >> 4) & 1) * 16);
    const uint32_t b_r  = (uint32_t)((lane & 7) + ((lane >> 4) & 1) * 8);
    const uint32_t b_cb = (uint32_t)(((lane >> 3) & 1) * 16);

    for (int t = 0; t < T; t++) {
        // In-flight groups: {t, t+1}; wait <=1 completes group t.
        CP_WAIT(1);
        __syncthreads();

        // Issue load(t+2) into stage (t+2)%3 == (t-1)%3 (readers passed the
        // barrier). Empty commits keep in-flight depth uniform.
        if (t + 2 < T) load_stage((t + 2) % 3, t + 2);
        else           CP_COMMIT();

        const uint32_t sb = su + (t % 3) * STAGE;

        // fp16 tile accumulators (zeroed per k-tile; K=64 accumulated in fp16)
        uint32_t hacc[4][4][2];
#pragma unroll
        for (int ms = 0; ms < 4; ms++)
#pragma unroll
            for (int n8 = 0; n8 < 4; n8++) {
                hacc[ms][n8][0] = 0u;
                hacc[ms][n8][1] = 0u;
            }

#pragma unroll
        for (int kk = 0; kk < BK / 16; kk++) {
            const uint32_t kb = (uint32_t)(kk * 32);
            uint32_t a[4][4];
#pragma unroll
            for (int ms = 0; ms < 4; ms++)
                ldsm_x4(a[ms], sb + A_OFF
                               + (uint32_t)(mw + ms * 16 + a_r) * ROWB + kb + a_cb);
            uint32_t b[2][4];
#pragma unroll
            for (int ns = 0; ns < 2; ns++)
                ldsm_x4(b[ns], sb + B_OFF
                               + (uint32_t)(nw + ns * 16 + b_r) * ROWB + kb + b_cb);
#pragma unroll
            for (int ms = 0; ms < 4; ms++)
#pragma unroll
                for (int n8 = 0; n8 < 4; n8++)
                    mma_fp16_hacc(hacc[ms][n8], a[ms],
                                  &b[n8 >> 1][(n8 & 1) * 2]);
        }

        // promote fp16 tile sums into persistent fp32 accumulators
#pragma unroll
        for (int ms = 0; ms < 4; ms++)
#pragma unroll
            for (int n8 = 0; n8 < 4; n8++) {
                float2 lo = __half22float2(
                    *reinterpret_cast<__half2*>(&hacc[ms][n8][0]));
                float2 hi = __half22float2(
                    *reinterpret_cast<__half2*>(&hacc[ms][n8][1]));
                acc[ms][n8][0] += lo.x;
                acc[ms][n8][1] += lo.y;
                acc[ms][n8][2] += hi.x;
                acc[ms][n8][3] += hi.y;
            }
    }

    // epilogue: fused bias, float2 stores
#pragma unroll
    for (int n8 = 0; n8 < 4; n8++) {
        const int n0 = bn + nw + n8 * 8 + 2 * (lane & 3);
        const float bv0 = BIAS[n0];
        const float bv1 = BIAS[n0 + 1];
#pragma unroll
        for (int ms = 0; ms < 4; ms++) {
            const int m0 = bm + mw + ms * 16 + (lane >> 2);
            float2 v;
            v.x = acc[ms][n8][0] + bv0;
            v.y = acc[ms][n8][1] + bv1;
            *reinterpret_cast<float2*>(Y + (size_t)m0 * N + n0) = v;
            v.x = acc[ms][n8][2] + bv0;
            v.y = acc[ms][n8][3] + bv1;
            *reinterpret_cast<float2*>(Y + (size_t)(m0 + 8) * N + n0) = v;
        }
    }
}

}  // namespace

extern "C" void kernel_launch(void* const* d_in, const int* in_sizes, int n_in,
                              void* d_out, int out_size) {
    const float* x    = (const float*)d_in[0];
    const int*   qw   = (const int*)d_in[1];
    const float* sc   = (const float*)d_in[2];
    const float* zp   = (const float*)d_in[3];
    const float* bias = (const float*)d_in[4];
    float* y = (float*)d_out;

    const int N = in_sizes[4];
    const long long K = ((long long)in_sizes[1] * 8) / N;
    const long long M = (long long)in_sizes[0] / K;

    cudaFuncSetAttribute(gemm_kernel, cudaFuncAttributeMaxDynamicSharedMemorySize,
                         SMEM_TOTAL);

    {   // x -> fp16
        long total4 = (long)M * K / 4;
        int blocks = (int)((total4 + 255) / 256);
        convert_x_kernel<<<blocks, 256>>>(x, total4);
    }
    {   // dequant W -> fp16
        int wordsPerRow = (int)(K / 8);
        int nGroups = (int)(K / 128);
        long totalWords = (long)N * wordsPerRow;
        int blocks = (int)((totalWords + 255) / 256);
        convert_w_kernel<<<blocks, 256>>>(qw, sc, zp, wordsPerRow, nGroups, totalWords);
    }
    {
        dim3 grid((unsigned)(N / BN), (unsigned)(M / BM));
        gemm_kernel<<<grid, THREADS, SMEM_TOTAL>>>(bias, y, (int)M, N, (int)K);
    }
}

// round 10
// speedup vs baseline: 1.1846x; 1.1846x over previous
#include <cuda_runtime.h>
#include <cuda_fp16.h>
#include <cstdint>

// Fused int4 group-dequant + GEMM via single-product fp16 mma.sync.
// Round 10: GEMM = round-7 champion (128x128 tile, 8 warps, 3-stage cp.async,
// 2 CTA/SM; measured at ~97% of the sm_103 legacy HMMA issue-rate wall of
// ~12.4 cyc/mma/SMSP). This round merges + widens the convert pre-passes
// (the only exposed non-GEMM time, ~40us) into one launch.

namespace {

constexpr int MMAX = 8192, NMAX = 4096, KMAX = 4096;

__device__ __half g_X[(size_t)MMAX * KMAX];
__device__ __half g_W[(size_t)NMAX * KMAX];

constexpr int BM = 128, BN = 128, BK = 64;
constexpr int THREADS = 256;
constexpr int ROWB = 144;                 // 64 fp16 = 128B + 16B pad
constexpr int A_OFF = 0;
constexpr int B_OFF = BM * ROWB;          // 18432
constexpr int STAGE = B_OFF + BN * ROWB;  // 36864
constexpr int NSTAGES = 3;
constexpr int SMEM_TOTAL = NSTAGES * STAGE;  // 110592 -> 2 CTAs/SM

__device__ __forceinline__ uint32_t smem_u32(const void* p) {
    uint32_t a;
    asm("{ .reg .u64 t; cvta.to.shared.u64 t, %1; cvt.u32.u64 %0, t; }"
        : "=r"(a) : "l"(p));
    return a;
}
__device__ __forceinline__ void cp16(uint32_t dst, const void* src) {
    asm volatile("cp.async.cg.shared.global [%0], [%1], 16;"
                 :: "r"(dst), "l"(src) : "memory");
}
#define CP_COMMIT() asm volatile("cp.async.commit_group;" ::: "memory")
#define CP_WAIT(n)  asm volatile("cp.async.wait_group %0;" :: "n"(n) : "memory")

__device__ __forceinline__ void ldsm_x4(uint32_t* r, uint32_t addr) {
    asm volatile("ldmatrix.sync.aligned.m8n8.x4.shared.b16 {%0,%1,%2,%3}, [%4];"
                 : "=r"(r[0]), "=r"(r[1]), "=r"(r[2]), "=r"(r[3]) : "r"(addr));
}
__device__ __forceinline__ void mma_fp16(float* c, const uint32_t* a,
                                         const uint32_t* b) {
    asm volatile(
        "mma.sync.aligned.m16n8k16.row.col.f32.f16.f16.f32 "
        "{%0,%1,%2,%3}, {%4,%5,%6,%7}, {%8,%9}, {%0,%1,%2,%3};"
        : "+f"(c[0]), "+f"(c[1]), "+f"(c[2]), "+f"(c[3])
        : "r"(a[0]), "r"(a[1]), "r"(a[2]), "r"(a[3]), "r"(b[0]), "r"(b[1]));
}

// ---- merged pre-pass ----
// Blocks [0, xBlocks):          x -> fp16 (32B in / 16B out per thread)
// Blocks [xBlocks, xBlocks+wB): dequant W -> fp16 (2 words in / 32B out)
__global__ __launch_bounds__(256)
void convert_kernel(const float* __restrict__ X,
                    const int*   __restrict__ QW,
                    const float* __restrict__ SC,
                    const float* __restrict__ ZP,
                    int xBlocks, int wordsPerRow, int nGroups) {
    if ((int)blockIdx.x < xBlocks) {
        // ---- X path: each thread converts 8 floats ----
        long i = (long)blockIdx.x * 256 + threadIdx.x;   // vec8 index
        const float4* src = reinterpret_cast<const float4*>(X) + 2 * i;
        float4 v0 = src[0];
        float4 v1 = src[1];
        __half2 h[4];
        h[0] = __floats2half2_rn(v0.x, v0.y);
        h[1] = __floats2half2_rn(v0.z, v0.w);
        h[2] = __floats2half2_rn(v1.x, v1.y);
        h[3] = __floats2half2_rn(v1.z, v1.w);
        reinterpret_cast<uint4*>(g_X)[i] = *reinterpret_cast<uint4*>(h);
    } else {
        // ---- W path: each thread dequants 2 int32 words (16 int4 vals) ----
        long tIdx = (long)((int)blockIdx.x - xBlocks) * 256 + threadIdx.x;
        long j = 2 * tIdx;                    // first word index
        int n = (int)(j / wordsPerRow);
        int w = (int)(j % wordsPerRow);
        int g = (w * 8) >> 7;                 // both words in same 128-group
        float s = SC[(size_t)n * nGroups + g];
        float z = ZP[(size_t)n * nGroups + g];
        float szn = -s * z;
        int2 qq = *reinterpret_cast<const int2*>(QW + j);
#pragma unroll
        for (int wd = 0; wd < 2; wd++) {
            unsigned q = (unsigned)(wd == 0 ? qq.x : qq.y);
            __half2 h[4];
#pragma unroll
            for (int k = 0; k < 4; k++) {
                float f0 = fmaf(s, (float)((q >> (8 * k)) & 0xFu), szn);
                float f1 = fmaf(s, (float)((q >> (8 * k + 4)) & 0xFu), szn);
                h[k] = __floats2half2_rn(f0, f1);
            }
            reinterpret_cast<uint4*>(g_W)[j + wd] = *reinterpret_cast<uint4*>(h);
        }
    }
}

// ---- main GEMM: 128x128 CTA, BK=64, 8 warps (2x4), warp tile 64x32 ----
__global__ __launch_bounds__(THREADS, 2)
void gemm_kernel(const float* __restrict__ BIAS, float* __restrict__ Y,
                 int M, int N, int K) {
    extern __shared__ char smem[];
    const uint32_t su = smem_u32(smem);
    const int tid  = threadIdx.x;
    const int lane = tid & 31;
    const int wid  = tid >> 5;
    const int bm = blockIdx.y * BM;
    const int bn = blockIdx.x * BN;
    const int mw = (wid >> 2) * 64;   // 2 warps along m
    const int nw = (wid & 3) * 32;    // 4 warps along n

    auto load_stage = [&](int s, int t) {
        const uint32_t sb = su + s * STAGE;
        const size_t k0 = (size_t)t * BK;
#pragma unroll
        for (int j = 0; j < 4; j++) {  // A: 128 rows x 8 x 16B
            int idx = tid + j * THREADS;
            int r = idx >> 3, c = idx & 7;
            cp16(sb + A_OFF + (uint32_t)(r * ROWB + c * 16),
                 (const char*)(g_X + (size_t)(bm + r) * K + k0) + c * 16);
        }
#pragma unroll
        for (int j = 0; j < 4; j++) {  // B: 128 rows x 8 x 16B
            int idx = tid + j * THREADS;
            int r = idx >> 3, c = idx & 7;
            cp16(sb + B_OFF + (uint32_t)(r * ROWB + c * 16),
                 (const char*)(g_W + (size_t)(bn + r) * K + k0) + c * 16);
        }
        CP_COMMIT();
    };

    float acc[4][4][4];
#pragma unroll
    for (int i = 0; i < 4; i++)
#pragma unroll
        for (int j = 0; j < 4; j++)
#pragma unroll
            for (int c = 0; c < 4; c++) acc[i][j][c] = 0.f;

    const int T = K / BK;  // 64
    load_stage(0, 0);
    load_stage(1, 1);

    // ldmatrix lane addressing
    const uint32_t a_r  = (uint32_t)((lane & 7) + ((lane >> 3) & 1) * 8);
    const uint32_t a_cb = (uint32_t)(((lane >> 4) & 1) * 16);
    const uint32_t b_r  = (uint32_t)((lane & 7) + ((lane >> 4) & 1) * 8);
    const uint32_t b_cb = (uint32_t)(((lane >> 3) & 1) * 16);

    for (int t = 0; t < T; t++) {
        // In-flight groups: {t, t+1}; wait <=1 completes group t.
        CP_WAIT(1);
        __syncthreads();

        // Issue load(t+2) into stage (t+2)%3 == (t-1)%3, whose readers all
        // passed the barrier above. Empty commits keep depth uniform.
        if (t + 2 < T) load_stage((t + 2) % 3, t + 2);
        else           CP_COMMIT();

        const uint32_t sb = su + (t % 3) * STAGE;

#pragma unroll
        for (int kk = 0; kk < BK / 16; kk++) {
            const uint32_t kb = (uint32_t)(kk * 32);
            uint32_t a[4][4];
#pragma unroll
            for (int ms = 0; ms < 4; ms++)
                ldsm_x4(a[ms], sb + A_OFF
                               + (uint32_t)(mw + ms * 16 + a_r) * ROWB + kb + a_cb);
            uint32_t b[2][4];
#pragma unroll
            for (int ns = 0; ns < 2; ns++)
                ldsm_x4(b[ns], sb + B_OFF
                               + (uint32_t)(nw + ns * 16 + b_r) * ROWB + kb + b_cb);
#pragma unroll
            for (int ms = 0; ms < 4; ms++)
#pragma unroll
                for (int n8 = 0; n8 < 4; n8++)
                    mma_fp16(acc[ms][n8], a[ms], &b[n8 >> 1][(n8 & 1) * 2]);
        }
    }

    // epilogue: fused bias, float2 stores
#pragma unroll
    for (int n8 = 0; n8 < 4; n8++) {
        const int n0 = bn + nw + n8 * 8 + 2 * (lane & 3);
        const float bv0 = BIAS[n0];
        const float bv1 = BIAS[n0 + 1];
#pragma unroll
        for (int ms = 0; ms < 4; ms++) {
            const int m0 = bm + mw + ms * 16 + (lane >> 2);
            float2 v;
            v.x = acc[ms][n8][0] + bv0;
            v.y = acc[ms][n8][1] + bv1;
            *reinterpret_cast<float2*>(Y + (size_t)m0 * N + n0) = v;
            v.x = acc[ms][n8][2] + bv0;
            v.y = acc[ms][n8][3] + bv1;
            *reinterpret_cast<float2*>(Y + (size_t)(m0 + 8) * N + n0) = v;
        }
    }
}

}  // namespace

extern "C" void kernel_launch(void* const* d_in, const int* in_sizes, int n_in,
                              void* d_out, int out_size) {
    const float* x    = (const float*)d_in[0];
    const int*   qw   = (const int*)d_in[1];
    const float* sc   = (const float*)d_in[2];
    const float* zp   = (const float*)d_in[3];
    const float* bias = (const float*)d_in[4];
    float* y = (float*)d_out;

    const int N = in_sizes[4];
    const long long K = ((long long)in_sizes[1] * 8) / N;
    const long long M = (long long)in_sizes[0] / K;

    cudaFuncSetAttribute(gemm_kernel, cudaFuncAttributeMaxDynamicSharedMemorySize,
                         SMEM_TOTAL);

    {   // merged pre-pass: x -> fp16 AND dequant W -> fp16 in one launch
        long xVec8   = (long)M * K / 8;              // 8 floats per thread
        int  xBlocks = (int)((xVec8 + 255) / 256);
        int  wordsPerRow = (int)(K / 8);
        int  nGroups     = (int)(K / 128);
        long wPairs   = (long)N * wordsPerRow / 2;   // 2 words per thread
        int  wBlocks  = (int)((wPairs + 255) / 256);
        convert_kernel<<<xBlocks + wBlocks, 256>>>(x, qw, sc, zp,
                                                   xBlocks, wordsPerRow, nGroups);
    }
    {
        dim3 grid((unsigned)(N / BN), (unsigned)(M / BM));
        gemm_kernel<<<grid, THREADS, SMEM_TOTAL>>>(bias, y, (int)M, N, (int)K);
    }
}